// round 1
// baseline (speedup 1.0000x reference)
#include <cuda_runtime.h>
#include <math.h>

#define KDIM 64
#define DEG 32
#define N0_MAX 65536

// hop-0 aggregate scratch: 65536 x 64 f32 = 16 MB (static __device__, no alloc)
__device__ float g_agg0[N0_MAX * KDIM];

__device__ __forceinline__ float warp_sum(float v) {
#pragma unroll
    for (int o = 16; o > 0; o >>= 1) v += __shfl_xor_sync(0xffffffffu, v, o);
    return v;
}

// renorm scale: min(1, 1/max(sqrt(ss), 1e-12))  ==  ss > 1 ? rsqrt(ss) : 1
__device__ __forceinline__ float renorm_scale(float ss) {
    return (ss > 1.0f) ? rsqrtf(ss) : 1.0f;
}

// One warp per hop-0 node. Lane l owns k-dims [2l, 2l+1].
__global__ void __launch_bounds__(256) hop0_kernel(
    const float* __restrict__ entity_emb,
    const int* __restrict__ node_ids0,
    const int* __restrict__ nbr0,
    int n0)
{
    const int node = blockIdx.x * (blockDim.x >> 5) + (threadIdx.x >> 5);
    const int lane = threadIdx.x & 31;
    if (node >= n0) return;

    // target row (renormed)
    const int tid = __ldg(node_ids0 + node);
    float2 t = __ldg((const float2*)(entity_emb + (size_t)tid * KDIM) + lane);
    const float tsc = renorm_scale(warp_sum(t.x * t.x + t.y * t.y));

    // all 32 neighbor indices, one per lane, broadcast via shuffle
    const int myidx = __ldg(nbr0 + (size_t)node * DEG + lane);

    float sx = 0.f, sy = 0.f, qx = 0.f, qy = 0.f;
#pragma unroll 4
    for (int d = 0; d < DEG; d++) {
        const int id = __shfl_sync(0xffffffffu, myidx, d);
        float2 e = __ldg((const float2*)(entity_emb + (size_t)id * KDIM) + lane);
        const float sc = renorm_scale(warp_sum(e.x * e.x + e.y * e.y));
        e.x *= sc; e.y *= sc;
        sx += e.x; sy += e.y;
        qx += e.x * e.x; qy += e.y * e.y;
    }

    float2 o;
    o.x = sx * sx - qx + t.x * tsc;
    o.y = sy * sy - qy + t.y * tsc;
    *((float2*)(g_agg0 + (size_t)node * KDIM) + lane) = o;
}

// One warp per batch row.
__global__ void __launch_bounds__(256) hop1_kernel(
    const float* __restrict__ entity_emb,
    const float* __restrict__ user_emb,
    const int* __restrict__ u,
    const int* __restrict__ item_ids,
    const int* __restrict__ nbr1_idx,
    float* __restrict__ out,
    int B)
{
    const int b = blockIdx.x * (blockDim.x >> 5) + (threadIdx.x >> 5);
    const int lane = threadIdx.x & 31;
    if (b >= B) return;

    const int myidx = __ldg(nbr1_idx + (size_t)b * DEG + lane);

    float sx = 0.f, sy = 0.f, qx = 0.f, qy = 0.f;
#pragma unroll 4
    for (int d = 0; d < DEG; d++) {
        const int id = __shfl_sync(0xffffffffu, myidx, d);
        const float2 e = *((const float2*)(g_agg0 + (size_t)id * KDIM) + lane);
        sx += e.x; sy += e.y;
        qx += e.x * e.x; qy += e.y * e.y;
    }

    // tgt1 = renorm(entity_emb[item_ids[b]])
    const int it = __ldg(item_ids + b);
    float2 t = __ldg((const float2*)(entity_emb + (size_t)it * KDIM) + lane);
    const float tsc = renorm_scale(warp_sum(t.x * t.x + t.y * t.y));

    float2 items;
    items.x = sx * sx - qx + t.x * tsc;
    items.y = sy * sy - qy + t.y * tsc;

    // users = renorm(user_emb[u[b]])
    const int uid = __ldg(u + b);
    float2 usr = __ldg((const float2*)(user_emb + (size_t)uid * KDIM) + lane);
    const float usc = renorm_scale(warp_sum(usr.x * usr.x + usr.y * usr.y));
    usr.x *= usc; usr.y *= usc;

    const float dot = warp_sum(usr.x * items.x + usr.y * items.y);
    if (lane == 0) out[b] = 1.0f / (1.0f + expf(-dot));
}

extern "C" void kernel_launch(void* const* d_in, const int* in_sizes, int n_in,
                              void* d_out, int out_size)
{
    const float* entity_emb = (const float*)d_in[0];
    const float* user_emb   = (const float*)d_in[1];
    // d_in[2..5] = Wa, ba, Wh, bh : dead code (softmax over singleton axis == 1)
    const int* u         = (const int*)d_in[6];
    const int* item_ids  = (const int*)d_in[7];
    const int* nbr1_idx  = (const int*)d_in[8];
    const int* node_ids0 = (const int*)d_in[9];
    const int* nbr0      = (const int*)d_in[10];

    const int B  = in_sizes[6];   // 2048
    const int n0 = in_sizes[9];   // 65536

    // hop 0: one warp per node, 8 warps per block
    {
        const int warps_per_block = 8;
        const int blocks = (n0 + warps_per_block - 1) / warps_per_block;
        hop0_kernel<<<blocks, warps_per_block * 32>>>(entity_emb, node_ids0, nbr0, n0);
    }
    // hop 1: one warp per batch row
    {
        const int warps_per_block = 8;
        const int blocks = (B + warps_per_block - 1) / warps_per_block;
        hop1_kernel<<<blocks, warps_per_block * 32>>>(
            entity_emb, user_emb, u, item_ids, nbr1_idx, (float*)d_out, B);
    }
}

// round 2
// speedup vs baseline: 1.1947x; 1.1947x over previous
#include <cuda_runtime.h>
#include <math.h>

#define KDIM 64
#define DEG 32
#define N0_MAX 65536

// hop-0 aggregate scratch: 65536 x 64 f32 = 16 MB (static __device__, no alloc)
__device__ float g_agg0[N0_MAX * KDIM];

// reduce across a 16-lane half-warp (xor 8,4,2,1)
__device__ __forceinline__ float half_sum(float v) {
#pragma unroll
    for (int o = 8; o > 0; o >>= 1) v += __shfl_xor_sync(0xffffffffu, v, o);
    return v;
}

// renorm scale: min(1, 1/max(sqrt(ss), 1e-12)) == ss > 1 ? rsqrt(ss) : 1
__device__ __forceinline__ float renorm_scale(float ss) {
    return (ss > 1.0f) ? rsqrtf(ss) : 1.0f;
}

// One warp per hop-0 node. Half-warp `sub` covers neighbors {16*sub + i};
// within a half-warp, lane sl owns k-dims [4*sl, 4*sl+3] via float4.
__global__ void __launch_bounds__(256) hop0_kernel(
    const float* __restrict__ entity_emb,
    const int* __restrict__ node_ids0,
    const int* __restrict__ nbr0,
    int n0)
{
    const int node = blockIdx.x * (blockDim.x >> 5) + (threadIdx.x >> 5);
    const int lane = threadIdx.x & 31;
    const int sub  = lane >> 4;          // which half-warp (0/1)
    const int sl   = lane & 15;          // lane within half-warp
    if (node >= n0) return;

    // all 32 neighbor indices, one per lane
    const int myidx = __ldg(nbr0 + (size_t)node * DEG + lane);

    float4 s = make_float4(0.f, 0.f, 0.f, 0.f);
    float4 q = make_float4(0.f, 0.f, 0.f, 0.f);

#pragma unroll 4
    for (int i = 0; i < DEG / 2; i++) {
        const int src = i + (sub << 4);
        const int id  = __shfl_sync(0xffffffffu, myidx, src);
        float4 e = __ldg((const float4*)(entity_emb + (size_t)id * KDIM) + sl);
        const float ss = half_sum(e.x * e.x + e.y * e.y + e.z * e.z + e.w * e.w);
        const float sc = renorm_scale(ss);
        e.x *= sc; e.y *= sc; e.z *= sc; e.w *= sc;
        s.x += e.x; s.y += e.y; s.z += e.z; s.w += e.w;
        q.x += e.x * e.x; q.y += e.y * e.y; q.z += e.z * e.z; q.w += e.w * e.w;
    }

    // combine the two half-warps' partial sums (same k-dims at lane ^ 16)
    s.x += __shfl_xor_sync(0xffffffffu, s.x, 16);
    s.y += __shfl_xor_sync(0xffffffffu, s.y, 16);
    s.z += __shfl_xor_sync(0xffffffffu, s.z, 16);
    s.w += __shfl_xor_sync(0xffffffffu, s.w, 16);
    q.x += __shfl_xor_sync(0xffffffffu, q.x, 16);
    q.y += __shfl_xor_sync(0xffffffffu, q.y, 16);
    q.z += __shfl_xor_sync(0xffffffffu, q.z, 16);
    q.w += __shfl_xor_sync(0xffffffffu, q.w, 16);

    // target row (renormed) — both halves load identical data (L1 broadcast)
    const int tid = __ldg(node_ids0 + node);
    float4 t = __ldg((const float4*)(entity_emb + (size_t)tid * KDIM) + sl);
    const float tsc = renorm_scale(half_sum(t.x * t.x + t.y * t.y + t.z * t.z + t.w * t.w));

    if (sub == 0) {
        float4 o;
        o.x = s.x * s.x - q.x + t.x * tsc;
        o.y = s.y * s.y - q.y + t.y * tsc;
        o.z = s.z * s.z - q.z + t.z * tsc;
        o.w = s.w * s.w - q.w + t.w * tsc;
        *((float4*)(g_agg0 + (size_t)node * KDIM) + sl) = o;
    }
}

// One warp per batch row, same two-rows-in-flight layout.
__global__ void __launch_bounds__(128) hop1_kernel(
    const float* __restrict__ entity_emb,
    const float* __restrict__ user_emb,
    const int* __restrict__ u,
    const int* __restrict__ item_ids,
    const int* __restrict__ nbr1_idx,
    float* __restrict__ out,
    int B)
{
    const int b = blockIdx.x * (blockDim.x >> 5) + (threadIdx.x >> 5);
    const int lane = threadIdx.x & 31;
    const int sub  = lane >> 4;
    const int sl   = lane & 15;
    if (b >= B) return;

    const int myidx = __ldg(nbr1_idx + (size_t)b * DEG + lane);

    float4 s = make_float4(0.f, 0.f, 0.f, 0.f);
    float4 q = make_float4(0.f, 0.f, 0.f, 0.f);

#pragma unroll 4
    for (int i = 0; i < DEG / 2; i++) {
        const int src = i + (sub << 4);
        const int id  = __shfl_sync(0xffffffffu, myidx, src);
        const float4 e = *((const float4*)(g_agg0 + (size_t)id * KDIM) + sl);
        s.x += e.x; s.y += e.y; s.z += e.z; s.w += e.w;
        q.x += e.x * e.x; q.y += e.y * e.y; q.z += e.z * e.z; q.w += e.w * e.w;
    }

    s.x += __shfl_xor_sync(0xffffffffu, s.x, 16);
    s.y += __shfl_xor_sync(0xffffffffu, s.y, 16);
    s.z += __shfl_xor_sync(0xffffffffu, s.z, 16);
    s.w += __shfl_xor_sync(0xffffffffu, s.w, 16);
    q.x += __shfl_xor_sync(0xffffffffu, q.x, 16);
    q.y += __shfl_xor_sync(0xffffffffu, q.y, 16);
    q.z += __shfl_xor_sync(0xffffffffu, q.z, 16);
    q.w += __shfl_xor_sync(0xffffffffu, q.w, 16);

    // tgt1 = renorm(entity_emb[item_ids[b]])
    const int it = __ldg(item_ids + b);
    float4 t = __ldg((const float4*)(entity_emb + (size_t)it * KDIM) + sl);
    const float tsc = renorm_scale(half_sum(t.x * t.x + t.y * t.y + t.z * t.z + t.w * t.w));

    float4 items;
    items.x = s.x * s.x - q.x + t.x * tsc;
    items.y = s.y * s.y - q.y + t.y * tsc;
    items.z = s.z * s.z - q.z + t.z * tsc;
    items.w = s.w * s.w - q.w + t.w * tsc;

    // users = renorm(user_emb[u[b]])
    const int uid = __ldg(u + b);
    float4 usr = __ldg((const float4*)(user_emb + (size_t)uid * KDIM) + sl);
    const float usc = renorm_scale(half_sum(usr.x * usr.x + usr.y * usr.y + usr.z * usr.z + usr.w * usr.w));

    const float dot = half_sum((usr.x * items.x + usr.y * items.y +
                                usr.z * items.z + usr.w * items.w) * usc);
    if (lane == 0) out[b] = 1.0f / (1.0f + expf(-dot));
}

extern "C" void kernel_launch(void* const* d_in, const int* in_sizes, int n_in,
                              void* d_out, int out_size)
{
    const float* entity_emb = (const float*)d_in[0];
    const float* user_emb   = (const float*)d_in[1];
    // d_in[2..5] = Wa, ba, Wh, bh : dead code (softmax over singleton axis == 1)
    const int* u         = (const int*)d_in[6];
    const int* item_ids  = (const int*)d_in[7];
    const int* nbr1_idx  = (const int*)d_in[8];
    const int* node_ids0 = (const int*)d_in[9];
    const int* nbr0      = (const int*)d_in[10];

    const int B  = in_sizes[6];   // 2048
    const int n0 = in_sizes[9];   // 65536

    // hop 0: one warp per node, 8 warps per block
    {
        const int wpb = 8;
        const int blocks = (n0 + wpb - 1) / wpb;
        hop0_kernel<<<blocks, wpb * 32>>>(entity_emb, node_ids0, nbr0, n0);
    }
    // hop 1: one warp per batch row, 4 warps per block (spread across SMs)
    {
        const int wpb = 4;
        const int blocks = (B + wpb - 1) / wpb;
        hop1_kernel<<<blocks, wpb * 32>>>(
            entity_emb, user_emb, u, item_ids, nbr1_idx, (float*)d_out, B);
    }
}

// round 3
// speedup vs baseline: 1.3176x; 1.1029x over previous
#include <cuda_runtime.h>
#include <math.h>

#define KDIM 64
#define DEG 32
#define N0_MAX 65536

// hop-0 aggregate scratch: 65536 x 64 f32 = 16 MB (static __device__, no alloc)
__device__ float g_agg0[N0_MAX * KDIM];

// reduce across a 16-lane half-warp (xor 8,4,2,1)
__device__ __forceinline__ float half_sum(float v) {
#pragma unroll
    for (int o = 8; o > 0; o >>= 1) v += __shfl_xor_sync(0xffffffffu, v, o);
    return v;
}

// renorm scale: min(1, 1/max(sqrt(ss), 1e-12)) == ss > 1 ? rsqrt(ss) : 1
__device__ __forceinline__ float renorm_scale(float ss) {
    return (ss > 1.0f) ? rsqrtf(ss) : 1.0f;
}

// One warp per hop-0 node. Half-warp `sub` covers neighbors {16*sub + i};
// within a half-warp, lane sl owns k-dims [4*sl, 4*sl+3] via float4.
// All 16 neighbor rows are prefetched into registers (MLP=16) before any
// reduction work touches them.
__global__ void __launch_bounds__(128) hop0_kernel(
    const float* __restrict__ entity_emb,
    const int* __restrict__ node_ids0,
    const int* __restrict__ nbr0,
    int n0)
{
    const int node = blockIdx.x * (blockDim.x >> 5) + (threadIdx.x >> 5);
    const int lane = threadIdx.x & 31;
    const int sub  = lane >> 4;          // which half-warp (0/1)
    const int sl   = lane & 15;          // lane within half-warp
    if (node >= n0) return;

    // all 32 neighbor indices, one per lane
    const int myidx = __ldg(nbr0 + (size_t)node * DEG + lane);
    const int tid   = __ldg(node_ids0 + node);

    // ---- batched prefetch: 16 independent 256B row reads + target row ----
    float4 e[16];
#pragma unroll
    for (int i = 0; i < 16; i++) {
        const int id = __shfl_sync(0xffffffffu, myidx, i + (sub << 4));
        e[i] = __ldg((const float4*)(entity_emb + (size_t)id * KDIM) + sl);
    }
    float4 t = __ldg((const float4*)(entity_emb + (size_t)tid * KDIM) + sl);

    // ---- FM accumulate with per-row renorm ----
    float4 s = make_float4(0.f, 0.f, 0.f, 0.f);
    float4 q = make_float4(0.f, 0.f, 0.f, 0.f);
#pragma unroll
    for (int i = 0; i < 16; i++) {
        const float ss = half_sum(e[i].x * e[i].x + e[i].y * e[i].y +
                                  e[i].z * e[i].z + e[i].w * e[i].w);
        const float sc = renorm_scale(ss);
        const float ex = e[i].x * sc, ey = e[i].y * sc;
        const float ez = e[i].z * sc, ew = e[i].w * sc;
        s.x += ex; s.y += ey; s.z += ez; s.w += ew;
        q.x += ex * ex; q.y += ey * ey; q.z += ez * ez; q.w += ew * ew;
    }

    // combine the two half-warps' partial sums (same k-dims at lane ^ 16)
    s.x += __shfl_xor_sync(0xffffffffu, s.x, 16);
    s.y += __shfl_xor_sync(0xffffffffu, s.y, 16);
    s.z += __shfl_xor_sync(0xffffffffu, s.z, 16);
    s.w += __shfl_xor_sync(0xffffffffu, s.w, 16);
    q.x += __shfl_xor_sync(0xffffffffu, q.x, 16);
    q.y += __shfl_xor_sync(0xffffffffu, q.y, 16);
    q.z += __shfl_xor_sync(0xffffffffu, q.z, 16);
    q.w += __shfl_xor_sync(0xffffffffu, q.w, 16);

    const float tsc = renorm_scale(half_sum(t.x * t.x + t.y * t.y +
                                            t.z * t.z + t.w * t.w));

    if (sub == 0) {
        float4 o;
        o.x = s.x * s.x - q.x + t.x * tsc;
        o.y = s.y * s.y - q.y + t.y * tsc;
        o.z = s.z * s.z - q.z + t.z * tsc;
        o.w = s.w * s.w - q.w + t.w * tsc;
        *((float4*)(g_agg0 + (size_t)node * KDIM) + sl) = o;
    }
}

// One warp per batch row, same batched-prefetch layout.
__global__ void __launch_bounds__(128) hop1_kernel(
    const float* __restrict__ entity_emb,
    const float* __restrict__ user_emb,
    const int* __restrict__ u,
    const int* __restrict__ item_ids,
    const int* __restrict__ nbr1_idx,
    float* __restrict__ out,
    int B)
{
    const int b = blockIdx.x * (blockDim.x >> 5) + (threadIdx.x >> 5);
    const int lane = threadIdx.x & 31;
    const int sub  = lane >> 4;
    const int sl   = lane & 15;
    if (b >= B) return;

    const int myidx = __ldg(nbr1_idx + (size_t)b * DEG + lane);
    const int it    = __ldg(item_ids + b);
    const int uid   = __ldg(u + b);

    // ---- batched prefetch: 16 rows from g_agg0 + item + user rows ----
    float4 e[16];
#pragma unroll
    for (int i = 0; i < 16; i++) {
        const int id = __shfl_sync(0xffffffffu, myidx, i + (sub << 4));
        e[i] = *((const float4*)(g_agg0 + (size_t)id * KDIM) + sl);
    }
    float4 t   = __ldg((const float4*)(entity_emb + (size_t)it * KDIM) + sl);
    float4 usr = __ldg((const float4*)(user_emb + (size_t)uid * KDIM) + sl);

    float4 s = make_float4(0.f, 0.f, 0.f, 0.f);
    float4 q = make_float4(0.f, 0.f, 0.f, 0.f);
#pragma unroll
    for (int i = 0; i < 16; i++) {
        s.x += e[i].x; s.y += e[i].y; s.z += e[i].z; s.w += e[i].w;
        q.x += e[i].x * e[i].x; q.y += e[i].y * e[i].y;
        q.z += e[i].z * e[i].z; q.w += e[i].w * e[i].w;
    }

    s.x += __shfl_xor_sync(0xffffffffu, s.x, 16);
    s.y += __shfl_xor_sync(0xffffffffu, s.y, 16);
    s.z += __shfl_xor_sync(0xffffffffu, s.z, 16);
    s.w += __shfl_xor_sync(0xffffffffu, s.w, 16);
    q.x += __shfl_xor_sync(0xffffffffu, q.x, 16);
    q.y += __shfl_xor_sync(0xffffffffu, q.y, 16);
    q.z += __shfl_xor_sync(0xffffffffu, q.z, 16);
    q.w += __shfl_xor_sync(0xffffffffu, q.w, 16);

    const float tsc = renorm_scale(half_sum(t.x * t.x + t.y * t.y +
                                            t.z * t.z + t.w * t.w));

    float4 items;
    items.x = s.x * s.x - q.x + t.x * tsc;
    items.y = s.y * s.y - q.y + t.y * tsc;
    items.z = s.z * s.z - q.z + t.z * tsc;
    items.w = s.w * s.w - q.w + t.w * tsc;

    const float usc = renorm_scale(half_sum(usr.x * usr.x + usr.y * usr.y +
                                            usr.z * usr.z + usr.w * usr.w));

    const float dot = half_sum((usr.x * items.x + usr.y * items.y +
                                usr.z * items.z + usr.w * items.w) * usc);
    if (lane == 0) out[b] = 1.0f / (1.0f + expf(-dot));
}

extern "C" void kernel_launch(void* const* d_in, const int* in_sizes, int n_in,
                              void* d_out, int out_size)
{
    const float* entity_emb = (const float*)d_in[0];
    const float* user_emb   = (const float*)d_in[1];
    // d_in[2..5] = Wa, ba, Wh, bh : dead code (softmax over singleton axis == 1)
    const int* u         = (const int*)d_in[6];
    const int* item_ids  = (const int*)d_in[7];
    const int* nbr1_idx  = (const int*)d_in[8];
    const int* node_ids0 = (const int*)d_in[9];
    const int* nbr0      = (const int*)d_in[10];

    const int B  = in_sizes[6];   // 2048
    const int n0 = in_sizes[9];   // 65536

    // hop 0: one warp per node, 4 warps per block (regs ~100/thread)
    {
        const int wpb = 4;
        const int blocks = (n0 + wpb - 1) / wpb;
        hop0_kernel<<<blocks, wpb * 32>>>(entity_emb, node_ids0, nbr0, n0);
    }
    // hop 1: one warp per batch row, 4 warps per block
    {
        const int wpb = 4;
        const int blocks = (B + wpb - 1) / wpb;
        hop1_kernel<<<blocks, wpb * 32>>>(
            entity_emb, user_emb, u, item_ids, nbr1_idx, (float*)d_out, B);
    }
}